// round 11
// baseline (speedup 1.0000x reference)
#include <cuda_runtime.h>
#include <cuda_fp16.h>
#include <cstdint>
#include <cfloat>

// Problem constants (fixed shapes for PQHotShared)
#define K_HOT   16384
#define R_DIM   64
#define D_DIM   4096
#define K_CB    2048
#define D_SUB   16
#define N_SV_U  (K_HOT * R_DIM / D_SUB)   // 65536
#define N_SV_B  (R_DIM * D_DIM / D_SUB)   // 16384

// Scratch (device globals — no allocation allowed)
__device__ __half g_Af[K_HOT * R_DIM];          // A as fp16 [m][k]
__device__ __half g_Bf[D_DIM * R_DIM];          // B^T as fp16 [n][k]
// Packed codebook, fp16 hi/lo split. Per cw 16 words:
//   words 0..7 : hi pairs, order [p0,p4,p1,p5,p2,p6,p3,p7] (p_i = dims 2i,2i+1)
//   words 8..15: lo pairs, same order
__device__ uint32_t g_cbpack[K_CB * 16];
__device__ float    g_hn[K_CB];                 // 0.5*||cb||^2

#define SW128(b) ((b) ^ (((b) >> 3) & 0x70))

__device__ __forceinline__ uint32_t smem_u32(const void* p) {
    uint32_t a;
    asm("{ .reg .u64 t; cvta.to.shared.u64 t, %1; cvt.u32.u64 %0, t; }"
        : "=r"(a) : "l"(p));
    return a;
}

__device__ __forceinline__ void ldmatrix_x4(uint32_t* r, uint32_t addr) {
    asm volatile("ldmatrix.sync.aligned.m8n8.x4.shared.b16 {%0,%1,%2,%3}, [%4];"
                 : "=r"(r[0]), "=r"(r[1]), "=r"(r[2]), "=r"(r[3]) : "r"(addr));
}

__device__ __forceinline__ void mma_f16(float* c, const uint32_t* a,
                                        const uint32_t* b) {
    asm volatile(
        "mma.sync.aligned.m16n8k16.row.col.f32.f16.f16.f32 "
        "{%0,%1,%2,%3}, {%4,%5,%6,%7}, {%8,%9}, {%0,%1,%2,%3};"
        : "+f"(c[0]), "+f"(c[1]), "+f"(c[2]), "+f"(c[3])
        : "r"(a[0]), "r"(a[1]), "r"(a[2]), "r"(a[3]), "r"(b[0]), "r"(b[1]));
}

__device__ __forceinline__ uint32_t pack_h2(float a, float b) {
    __half2 h = __floats2half2_rn(a, b);   // a -> low half (even k)
    return *(uint32_t*)&h;
}

// ---------------------------------------------------------------------------
// Codebook prep: fp16 hi/lo split, packed for direct mma B-fragment loads,
// plus half squared norms (fp32).
// ---------------------------------------------------------------------------
__global__ __launch_bounds__(256) void cb_prep_kernel(const float* __restrict__ cb)
{
    int cw = blockIdx.x * 256 + threadIdx.x;
    if (cw >= K_CB) return;
    float v[D_SUB];
    float hn = 0.f;
    #pragma unroll
    for (int j = 0; j < D_SUB; ++j) {
        v[j] = cb[cw * D_SUB + j];
        hn = fmaf(v[j], v[j], hn);
    }
    g_hn[cw] = 0.5f * hn;

    float hi[D_SUB], lo[D_SUB];
    #pragma unroll
    for (int j = 0; j < D_SUB; ++j) {
        float h = __half2float(__float2half_rn(v[j]));
        hi[j] = h;
        lo[j] = v[j] - h;
    }
    uint32_t w[16];
    #pragma unroll
    for (int i = 0; i < 4; ++i) {
        int p0 = i, p1 = i + 4;
        w[2 * i]     = pack_h2(hi[2 * p0], hi[2 * p0 + 1]);
        w[2 * i + 1] = pack_h2(hi[2 * p1], hi[2 * p1 + 1]);
        w[8 + 2 * i]     = pack_h2(lo[2 * p0], lo[2 * p0 + 1]);
        w[8 + 2 * i + 1] = pack_h2(lo[2 * p1], lo[2 * p1 + 1]);
    }
    uint4* dst = (uint4*)&g_cbpack[cw * 16];
    #pragma unroll
    for (int q = 0; q < 4; ++q)
        dst[q] = make_uint4(w[4 * q], w[4 * q + 1], w[4 * q + 2], w[4 * q + 3]);
}

// ---------------------------------------------------------------------------
// Fused PQ argmin via fp16-split m16n8k16 mma. Three INDEPENDENT accumulator
// chains per nt (no RAW serialization between the 3 mma). One m16 tile per
// warp, 128 rows per block, 640 blocks, QCH=256 (26 KB smem -> 3 CTAs/SM).
// Blocks [0,512): U rows; [512,640): B rows (written transposed).
// ---------------------------------------------------------------------------
#define QROWS 128
#define QCH   256
#define QST   24          // words per codeword row in smem (conflict-free)

__global__ __launch_bounds__(256, 3) void pq_argmin_kernel(
    const float* __restrict__ U, const float* __restrict__ B,
    const float* __restrict__ rsU, const float* __restrict__ rsB,
    const float* __restrict__ cb,
    __half* __restrict__ Af, __half* __restrict__ Btf)
{
    __shared__ uint32_t cb_sh[QCH * QST];       // 24.5 KB
    __shared__ float hn_sh[QCH];                // 1 KB
    __shared__ int idx_sh[QROWS];

    const int tid = threadIdx.x;
    const int warp = tid >> 5, lane = tid & 31;
    const int g = lane >> 2, t = lane & 3;
    const bool isU = blockIdx.x < 512;
    const int svbase = isU ? blockIdx.x * QROWS : (blockIdx.x - 512) * QROWS;
    const float* Wp = isU ? U : B;

    // A fragments (fp16 hi/lo), one m16 tile per warp:
    // a0=(row g, kp t), a1=(row g+8, kp t), a2=(row g, kp t+4), a3=(row g+8, kp t+4)
    uint32_t ahi[4], alo[4];
    #pragma unroll
    for (int rh = 0; rh < 2; ++rh) {
        int r = svbase + warp * 16 + rh * 8 + g;
        int off; float rsv;
        if (isU) { off = (r >> 2) * 64 + (r & 3) * 16;     rsv = rsU[r >> 2]; }
        else     { off = (r >> 8) * 4096 + (r & 255) * 16; rsv = rsB[r >> 8]; }
        float v0 = Wp[off + 2 * t]     / rsv;
        float v1 = Wp[off + 2 * t + 1] / rsv;
        float v2 = Wp[off + 8 + 2 * t]     / rsv;
        float v3 = Wp[off + 8 + 2 * t + 1] / rsv;
        float h0 = __half2float(__float2half_rn(v0));
        float h1 = __half2float(__float2half_rn(v1));
        float h2 = __half2float(__float2half_rn(v2));
        float h3 = __half2float(__float2half_rn(v3));
        ahi[rh]     = pack_h2(h0, h1);
        ahi[2 + rh] = pack_h2(h2, h3);
        alo[rh]     = pack_h2(v0 - h0, v1 - h1);
        alo[2 + rh] = pack_h2(v2 - h2, v3 - h3);
    }

    float bs[2]; int bi[2];
    #pragma unroll
    for (int q = 0; q < 2; ++q) { bs[q] = -FLT_MAX; bi[q] = 0; }

    for (int ch = 0; ch < K_CB; ch += QCH) {
        __syncthreads();
        {
            const uint4* src = (const uint4*)(g_cbpack + ch * 16);
            #pragma unroll
            for (int it = 0; it < 4; ++it) {
                int i = tid + it * 256;
                int cw = i >> 2, q = i & 3;
                *(uint4*)&cb_sh[cw * QST + q * 4] = src[i];
            }
            hn_sh[tid] = g_hn[ch + tid];
        }
        __syncthreads();

        #pragma unroll 4
        for (int nt = 0; nt < QCH / 8; ++nt) {
            const int n0 = nt * 8;
            const uint32_t* cwp = &cb_sh[(n0 + g) * QST];
            uint2 bhp = *(const uint2*)(cwp + 2 * t);        // (h_t, h_{t+4})
            uint2 blp = *(const uint2*)(cwp + 8 + 2 * t);    // (l_t, l_{t+4})
            uint32_t bh[2] = {bhp.x, bhp.y};
            uint32_t bl[2] = {blp.x, blp.y};
            float2 hnp = *(const float2*)&hn_sh[n0 + 2 * t];
            const int base = ch + n0 + 2 * t;
            // three independent mma chains (no accumulator RAW between them)
            float c1[4] = {-hnp.x, -hnp.y, -hnp.x, -hnp.y};
            float c2[4] = {0.f, 0.f, 0.f, 0.f};
            float c3[4] = {0.f, 0.f, 0.f, 0.f};
            mma_f16(c1, ahi, bh);
            mma_f16(c2, ahi, bl);
            mma_f16(c3, alo, bh);
            float s0 = (c1[0] + c2[0]) + c3[0];
            float s1 = (c1[1] + c2[1]) + c3[1];
            float s2 = (c1[2] + c2[2]) + c3[2];
            float s3 = (c1[3] + c2[3]) + c3[3];
            if (s0 > bs[0]) { bs[0] = s0; bi[0] = base; }
            if (s1 > bs[0]) { bs[0] = s1; bi[0] = base + 1; }
            if (s2 > bs[1]) { bs[1] = s2; bi[1] = base; }
            if (s3 > bs[1]) { bs[1] = s3; bi[1] = base + 1; }
        }
    }

    // Reduce argmax across the 4 t-lanes of each row quad (tie -> smaller idx)
    #pragma unroll
    for (int q = 0; q < 2; ++q) {
        float s = bs[q]; int i0 = bi[q];
        #pragma unroll
        for (int d = 1; d <= 2; d <<= 1) {
            float so = __shfl_xor_sync(0xffffffffu, s, d);
            int   io = __shfl_xor_sync(0xffffffffu, i0, d);
            if (so > s || (so == s && io < i0)) { s = so; i0 = io; }
        }
        if (t == 0)
            idx_sh[warp * 16 + q * 8 + g] = i0;
    }
    __syncwarp();

    // Dequant write: lanes 0..15 each own one row of the warp's 16.
    if (lane < 16) {
        const int rloc = warp * 16 + lane;
        const int w = idx_sh[rloc];
        const int r = svbase + rloc;
        const float* cbr = cb + w * D_SUB;
        if (isU) {
            const int urow = r >> 2;
            const float rsv = rsU[urow];
            const int off = urow * 64 + (r & 3) * 16;
            uint32_t* df = (uint32_t*)(Af + off);
            #pragma unroll
            for (int p = 0; p < 8; ++p)
                df[p] = pack_h2(cbr[2 * p] * rsv, cbr[2 * p + 1] * rsv);
        } else {
            const int brow = r >> 8;
            const float rsv = rsB[brow];
            const int nb = (r & 255) * 16;
            #pragma unroll
            for (int j = 0; j < D_SUB; ++j)
                Btf[(nb + j) * 64 + brow] = __float2half_rn(cbr[j] * rsv);
        }
    }
}

// ---------------------------------------------------------------------------
// fp16 single-pass GEMM on mma.sync (verified rounds 7-10, unchanged):
// C[16384,4096] = Af @ Bf^T, fp32 acc.
// ---------------------------------------------------------------------------
#define OFF_AF 0
#define OFF_BF 16384
#define GEMM_SMEM (2 * 16384)

__device__ __forceinline__ void load_tile_128x64(
    char* smem, int off, const __half* __restrict__ src, int tid)
{
    #pragma unroll
    for (int it = 0; it < 4; ++it) {
        int i = tid + it * 256;
        int m = i >> 3, q = i & 7;
        uint32_t b = (uint32_t)(m * 128 + q * 16);
        *(uint4*)(smem + off + SW128(b)) = ((const uint4*)(src + m * 64))[q];
    }
}

__global__ __launch_bounds__(256, 2) void mma_gemm_kernel(
    const __half* __restrict__ Af, const __half* __restrict__ Bf,
    float* __restrict__ C)
{
    extern __shared__ char smem[];
    const uint32_t sbase = smem_u32(smem);
    const int tid = threadIdx.x;
    const int wid = tid >> 5, lane = tid & 31;
    const int row0 = blockIdx.y * 128;
    const int col0 = blockIdx.x * 128;

    load_tile_128x64(smem, OFF_AF, Af + (size_t)row0 * R_DIM, tid);
    load_tile_128x64(smem, OFF_BF, Bf + (size_t)col0 * R_DIM, tid);
    __syncthreads();

    const int warp_m = wid & 3;
    const int warp_n = wid >> 2;
    const int mbase = warp_m * 32;
    const int nbase = warp_n * 64;

    const int a_row = mbase + (lane & 15);
    const int a_kb  = (lane >> 4) * 16;
    const int b_nrow = nbase + (lane & 7) + (lane >> 4) * 8;
    const int b_kb   = ((lane >> 3) & 1) * 16;

    float acc[2][8][4];
    #pragma unroll
    for (int mt = 0; mt < 2; ++mt)
        #pragma unroll
        for (int nt = 0; nt < 8; ++nt)
            #pragma unroll
            for (int q = 0; q < 4; ++q) acc[mt][nt][q] = 0.f;

    #pragma unroll
    for (int k = 0; k < 4; ++k) {
        uint32_t a[2][4];
        #pragma unroll
        for (int mt = 0; mt < 2; ++mt) {
            uint32_t b = (uint32_t)((a_row + mt * 16) * 128 + k * 32 + a_kb);
            ldmatrix_x4(a[mt], sbase + OFF_AF + SW128(b));
        }
        uint32_t bf[8][2];
        #pragma unroll
        for (int np = 0; np < 4; ++np) {
            uint32_t b = (uint32_t)((b_nrow + np * 16) * 128 + k * 32 + b_kb);
            uint32_t r[4];
            ldmatrix_x4(r, sbase + OFF_BF + SW128(b));
            bf[np * 2][0] = r[0]; bf[np * 2][1] = r[1];
            bf[np * 2 + 1][0] = r[2]; bf[np * 2 + 1][1] = r[3];
        }
        #pragma unroll
        for (int mt = 0; mt < 2; ++mt)
            #pragma unroll
            for (int nt = 0; nt < 8; ++nt)
                mma_f16(acc[mt][nt], a[mt], bf[nt]);
    }

    const int g = lane >> 2, t = lane & 3;
    #pragma unroll
    for (int mt = 0; mt < 2; ++mt) {
        float* Cr0 = C + (size_t)(row0 + mbase + mt * 16 + g) * D_DIM + col0 + nbase;
        float* Cr1 = Cr0 + 8 * D_DIM;
        #pragma unroll
        for (int nt = 0; nt < 8; ++nt) {
            *(float2*)(Cr0 + nt * 8 + t * 2) =
                make_float2(acc[mt][nt][0], acc[mt][nt][1]);
            *(float2*)(Cr1 + nt * 8 + t * 2) =
                make_float2(acc[mt][nt][2], acc[mt][nt][3]);
        }
    }
}

// ---------------------------------------------------------------------------
extern "C" void kernel_launch(void* const* d_in, const int* in_sizes, int n_in,
                              void* d_out, int out_size)
{
    (void)in_sizes; (void)n_in; (void)out_size;
    const float* U   = (const float*)d_in[0];
    const float* B   = (const float*)d_in[1];
    const float* rsU = (const float*)d_in[2];
    const float* rsB = (const float*)d_in[3];
    const float* cb  = (const float*)d_in[4];
    float* out = (float*)d_out;

    __half *af, *bf;
    cudaGetSymbolAddress((void**)&af, g_Af);
    cudaGetSymbolAddress((void**)&bf, g_Bf);

    cb_prep_kernel<<<8, 256>>>(cb);
    pq_argmin_kernel<<<640, 256>>>(U, B, rsU, rsB, cb, af, bf);

    cudaFuncSetAttribute(mma_gemm_kernel,
                         cudaFuncAttributeMaxDynamicSharedMemorySize, GEMM_SMEM);
    dim3 grid(D_DIM / 128, K_HOT / 128);
    mma_gemm_kernel<<<grid, 256, GEMM_SMEM>>>(af, bf, out);
}

// round 12
// speedup vs baseline: 1.0260x; 1.0260x over previous
#include <cuda_runtime.h>
#include <cuda_fp16.h>
#include <cstdint>
#include <cfloat>

// Problem constants (fixed shapes for PQHotShared)
#define K_HOT   16384
#define R_DIM   64
#define D_DIM   4096
#define K_CB    2048
#define D_SUB   16
#define N_SV_U  (K_HOT * R_DIM / D_SUB)   // 65536
#define N_SV_B  (R_DIM * D_DIM / D_SUB)   // 16384

// Scratch (device globals — no allocation allowed)
__device__ __half g_Af[K_HOT * R_DIM];          // A as fp16 [m][k]
__device__ __half g_Bf[D_DIM * R_DIM];          // B^T as fp16 [n][k]
// Fragment-fused packed codebook. Per cw 16 words; for t in 0..3:
//   word[4t+0] = hi pair t      (dims 2t, 2t+1)
//   word[4t+1] = hi pair t+4    (dims 2t+8, 2t+9)
//   word[4t+2] = lo pair t
//   word[4t+3] = lo pair t+4
// => lane (g,t) fetches its full mma B operand with ONE LDS.128.
__device__ uint32_t g_cbpack[K_CB * 16];
__device__ float    g_hn[K_CB];                 // 0.5*||cb||^2

#define SW128(b) ((b) ^ (((b) >> 3) & 0x70))

__device__ __forceinline__ uint32_t smem_u32(const void* p) {
    uint32_t a;
    asm("{ .reg .u64 t; cvta.to.shared.u64 t, %1; cvt.u32.u64 %0, t; }"
        : "=r"(a) : "l"(p));
    return a;
}

__device__ __forceinline__ void ldmatrix_x4(uint32_t* r, uint32_t addr) {
    asm volatile("ldmatrix.sync.aligned.m8n8.x4.shared.b16 {%0,%1,%2,%3}, [%4];"
                 : "=r"(r[0]), "=r"(r[1]), "=r"(r[2]), "=r"(r[3]) : "r"(addr));
}

__device__ __forceinline__ void mma_f16(float* c, const uint32_t* a,
                                        const uint32_t* b) {
    asm volatile(
        "mma.sync.aligned.m16n8k16.row.col.f32.f16.f16.f32 "
        "{%0,%1,%2,%3}, {%4,%5,%6,%7}, {%8,%9}, {%0,%1,%2,%3};"
        : "+f"(c[0]), "+f"(c[1]), "+f"(c[2]), "+f"(c[3])
        : "r"(a[0]), "r"(a[1]), "r"(a[2]), "r"(a[3]), "r"(b[0]), "r"(b[1]));
}

__device__ __forceinline__ uint32_t pack_h2(float a, float b) {
    __half2 h = __floats2half2_rn(a, b);   // a -> low half (even k)
    return *(uint32_t*)&h;
}

// ---------------------------------------------------------------------------
// Codebook prep: fp16 hi/lo split into the fragment-fused layout + half norms.
// ---------------------------------------------------------------------------
__global__ __launch_bounds__(256) void cb_prep_kernel(const float* __restrict__ cb)
{
    int cw = blockIdx.x * 256 + threadIdx.x;
    if (cw >= K_CB) return;
    float v[D_SUB];
    float hn = 0.f;
    #pragma unroll
    for (int j = 0; j < D_SUB; ++j) {
        v[j] = cb[cw * D_SUB + j];
        hn = fmaf(v[j], v[j], hn);
    }
    g_hn[cw] = 0.5f * hn;

    float hi[D_SUB], lo[D_SUB];
    #pragma unroll
    for (int j = 0; j < D_SUB; ++j) {
        float h = __half2float(__float2half_rn(v[j]));
        hi[j] = h;
        lo[j] = v[j] - h;
    }
    uint32_t w[16];
    #pragma unroll
    for (int t = 0; t < 4; ++t) {
        w[4 * t + 0] = pack_h2(hi[2 * t],     hi[2 * t + 1]);
        w[4 * t + 1] = pack_h2(hi[2 * t + 8], hi[2 * t + 9]);
        w[4 * t + 2] = pack_h2(lo[2 * t],     lo[2 * t + 1]);
        w[4 * t + 3] = pack_h2(lo[2 * t + 8], lo[2 * t + 9]);
    }
    uint4* dst = (uint4*)&g_cbpack[cw * 16];
    #pragma unroll
    for (int q = 0; q < 4; ++q)
        dst[q] = make_uint4(w[4 * q], w[4 * q + 1], w[4 * q + 2], w[4 * q + 3]);
}

// ---------------------------------------------------------------------------
// Fused PQ argmin via fp16-split m16n8k16 mma (round-10 math bit-for-bit:
// chained accumulator, same order). One m16 tile per warp, 128 rows/block,
// 640 blocks. Per nt-step: ONE LDS.128 (B frags) + ONE LDS.64 (norms).
// Blocks [0,512): U rows; [512,640): B rows (written transposed).
// ---------------------------------------------------------------------------
#define QROWS 128
#define QCH   512

__global__ __launch_bounds__(256) void pq_argmin_kernel(
    const float* __restrict__ U, const float* __restrict__ B,
    const float* __restrict__ rsU, const float* __restrict__ rsB,
    const float* __restrict__ cb,
    __half* __restrict__ Af, __half* __restrict__ Btf)
{
    __shared__ uint32_t cb_sh[QCH * 16];        // 32 KB, stride-16 rows
    __shared__ float hn_sh[QCH];                // 2 KB
    __shared__ int idx_sh[QROWS];

    const int tid = threadIdx.x;
    const int warp = tid >> 5, lane = tid & 31;
    const int g = lane >> 2, t = lane & 3;
    const bool isU = blockIdx.x < 512;
    const int svbase = isU ? blockIdx.x * QROWS : (blockIdx.x - 512) * QROWS;
    const float* Wp = isU ? U : B;

    // A fragments (fp16 hi/lo), one m16 tile per warp:
    // a0=(row g, kp t), a1=(row g+8, kp t), a2=(row g, kp t+4), a3=(row g+8, kp t+4)
    uint32_t ahi[4], alo[4];
    #pragma unroll
    for (int rh = 0; rh < 2; ++rh) {
        int r = svbase + warp * 16 + rh * 8 + g;
        int off; float rsv;
        if (isU) { off = (r >> 2) * 64 + (r & 3) * 16;     rsv = rsU[r >> 2]; }
        else     { off = (r >> 8) * 4096 + (r & 255) * 16; rsv = rsB[r >> 8]; }
        float v0 = Wp[off + 2 * t]     / rsv;
        float v1 = Wp[off + 2 * t + 1] / rsv;
        float v2 = Wp[off + 8 + 2 * t]     / rsv;
        float v3 = Wp[off + 8 + 2 * t + 1] / rsv;
        float h0 = __half2float(__float2half_rn(v0));
        float h1 = __half2float(__float2half_rn(v1));
        float h2 = __half2float(__float2half_rn(v2));
        float h3 = __half2float(__float2half_rn(v3));
        ahi[rh]     = pack_h2(h0, h1);
        ahi[2 + rh] = pack_h2(h2, h3);
        alo[rh]     = pack_h2(v0 - h0, v1 - h1);
        alo[2 + rh] = pack_h2(v2 - h2, v3 - h3);
    }

    float bs[2]; int bi[2];
    #pragma unroll
    for (int q = 0; q < 2; ++q) { bs[q] = -FLT_MAX; bi[q] = 0; }

    for (int ch = 0; ch < K_CB; ch += QCH) {
        __syncthreads();
        {
            // straight linear copy: packed rows are exactly 16 words
            const uint4* src = (const uint4*)(g_cbpack + ch * 16);
            uint4* dst = (uint4*)cb_sh;
            #pragma unroll
            for (int it = 0; it < 8; ++it)
                dst[tid + it * 256] = src[tid + it * 256];
            hn_sh[tid] = g_hn[ch + tid];
            hn_sh[tid + 256] = g_hn[ch + tid + 256];
        }
        __syncthreads();

        #pragma unroll 4
        for (int nt = 0; nt < QCH / 8; ++nt) {
            const int n0 = nt * 8;
            uint4 frag = *(const uint4*)&cb_sh[(n0 + g) * 16 + 4 * t];
            uint32_t bh[2] = {frag.x, frag.y};
            uint32_t bl[2] = {frag.z, frag.w};
            float2 hnp = *(const float2*)&hn_sh[n0 + 2 * t];
            const int base = ch + n0 + 2 * t;
            float c[4] = {-hnp.x, -hnp.y, -hnp.x, -hnp.y};
            mma_f16(c, ahi, bh);
            mma_f16(c, ahi, bl);
            mma_f16(c, alo, bh);
            if (c[0] > bs[0]) { bs[0] = c[0]; bi[0] = base; }
            if (c[1] > bs[0]) { bs[0] = c[1]; bi[0] = base + 1; }
            if (c[2] > bs[1]) { bs[1] = c[2]; bi[1] = base; }
            if (c[3] > bs[1]) { bs[1] = c[3]; bi[1] = base + 1; }
        }
    }

    // Reduce argmax across the 4 t-lanes of each row quad (tie -> smaller idx)
    #pragma unroll
    for (int q = 0; q < 2; ++q) {
        float s = bs[q]; int i0 = bi[q];
        #pragma unroll
        for (int d = 1; d <= 2; d <<= 1) {
            float so = __shfl_xor_sync(0xffffffffu, s, d);
            int   io = __shfl_xor_sync(0xffffffffu, i0, d);
            if (so > s || (so == s && io < i0)) { s = so; i0 = io; }
        }
        if (t == 0)
            idx_sh[warp * 16 + q * 8 + g] = i0;
    }
    __syncwarp();

    // Dequant write: lanes 0..15 each own one row of the warp's 16.
    if (lane < 16) {
        const int rloc = warp * 16 + lane;
        const int w = idx_sh[rloc];
        const int r = svbase + rloc;
        const float* cbr = cb + w * D_SUB;
        if (isU) {
            const int urow = r >> 2;
            const float rsv = rsU[urow];
            const int off = urow * 64 + (r & 3) * 16;
            uint32_t* df = (uint32_t*)(Af + off);
            #pragma unroll
            for (int p = 0; p < 8; ++p)
                df[p] = pack_h2(cbr[2 * p] * rsv, cbr[2 * p + 1] * rsv);
        } else {
            const int brow = r >> 8;
            const float rsv = rsB[brow];
            const int nb = (r & 255) * 16;
            #pragma unroll
            for (int j = 0; j < D_SUB; ++j)
                Btf[(nb + j) * 64 + brow] = __float2half_rn(cbr[j] * rsv);
        }
    }
}

// ---------------------------------------------------------------------------
// fp16 single-pass GEMM on mma.sync (verified rounds 7-11, unchanged):
// C[16384,4096] = Af @ Bf^T, fp32 acc.
// ---------------------------------------------------------------------------
#define OFF_AF 0
#define OFF_BF 16384
#define GEMM_SMEM (2 * 16384)

__device__ __forceinline__ void load_tile_128x64(
    char* smem, int off, const __half* __restrict__ src, int tid)
{
    #pragma unroll
    for (int it = 0; it < 4; ++it) {
        int i = tid + it * 256;
        int m = i >> 3, q = i & 7;
        uint32_t b = (uint32_t)(m * 128 + q * 16);
        *(uint4*)(smem + off + SW128(b)) = ((const uint4*)(src + m * 64))[q];
    }
}

__global__ __launch_bounds__(256, 2) void mma_gemm_kernel(
    const __half* __restrict__ Af, const __half* __restrict__ Bf,
    float* __restrict__ C)
{
    extern __shared__ char smem[];
    const uint32_t sbase = smem_u32(smem);
    const int tid = threadIdx.x;
    const int wid = tid >> 5, lane = tid & 31;
    const int row0 = blockIdx.y * 128;
    const int col0 = blockIdx.x * 128;

    load_tile_128x64(smem, OFF_AF, Af + (size_t)row0 * R_DIM, tid);
    load_tile_128x64(smem, OFF_BF, Bf + (size_t)col0 * R_DIM, tid);
    __syncthreads();

    const int warp_m = wid & 3;
    const int warp_n = wid >> 2;
    const int mbase = warp_m * 32;
    const int nbase = warp_n * 64;

    const int a_row = mbase + (lane & 15);
    const int a_kb  = (lane >> 4) * 16;
    const int b_nrow = nbase + (lane & 7) + (lane >> 4) * 8;
    const int b_kb   = ((lane >> 3) & 1) * 16;

    float acc[2][8][4];
    #pragma unroll
    for (int mt = 0; mt < 2; ++mt)
        #pragma unroll
        for (int nt = 0; nt < 8; ++nt)
            #pragma unroll
            for (int q = 0; q < 4; ++q) acc[mt][nt][q] = 0.f;

    #pragma unroll
    for (int k = 0; k < 4; ++k) {
        uint32_t a[2][4];
        #pragma unroll
        for (int mt = 0; mt < 2; ++mt) {
            uint32_t b = (uint32_t)((a_row + mt * 16) * 128 + k * 32 + a_kb);
            ldmatrix_x4(a[mt], sbase + OFF_AF + SW128(b));
        }
        uint32_t bf[8][2];
        #pragma unroll
        for (int np = 0; np < 4; ++np) {
            uint32_t b = (uint32_t)((b_nrow + np * 16) * 128 + k * 32 + b_kb);
            uint32_t r[4];
            ldmatrix_x4(r, sbase + OFF_BF + SW128(b));
            bf[np * 2][0] = r[0]; bf[np * 2][1] = r[1];
            bf[np * 2 + 1][0] = r[2]; bf[np * 2 + 1][1] = r[3];
        }
        #pragma unroll
        for (int mt = 0; mt < 2; ++mt)
            #pragma unroll
            for (int nt = 0; nt < 8; ++nt)
                mma_f16(acc[mt][nt], a[mt], bf[nt]);
    }

    const int g = lane >> 2, t = lane & 3;
    #pragma unroll
    for (int mt = 0; mt < 2; ++mt) {
        float* Cr0 = C + (size_t)(row0 + mbase + mt * 16 + g) * D_DIM + col0 + nbase;
        float* Cr1 = Cr0 + 8 * D_DIM;
        #pragma unroll
        for (int nt = 0; nt < 8; ++nt) {
            *(float2*)(Cr0 + nt * 8 + t * 2) =
                make_float2(acc[mt][nt][0], acc[mt][nt][1]);
            *(float2*)(Cr1 + nt * 8 + t * 2) =
                make_float2(acc[mt][nt][2], acc[mt][nt][3]);
        }
    }
}

// ---------------------------------------------------------------------------
extern "C" void kernel_launch(void* const* d_in, const int* in_sizes, int n_in,
                              void* d_out, int out_size)
{
    (void)in_sizes; (void)n_in; (void)out_size;
    const float* U   = (const float*)d_in[0];
    const float* B   = (const float*)d_in[1];
    const float* rsU = (const float*)d_in[2];
    const float* rsB = (const float*)d_in[3];
    const float* cb  = (const float*)d_in[4];
    float* out = (float*)d_out;

    __half *af, *bf;
    cudaGetSymbolAddress((void**)&af, g_Af);
    cudaGetSymbolAddress((void**)&bf, g_Bf);

    cb_prep_kernel<<<8, 256>>>(cb);
    pq_argmin_kernel<<<640, 256>>>(U, B, rsU, rsB, cb, af, bf);

    cudaFuncSetAttribute(mma_gemm_kernel,
                         cudaFuncAttributeMaxDynamicSharedMemorySize, GEMM_SMEM);
    dim3 grid(D_DIM / 128, K_HOT / 128);
    mma_gemm_kernel<<<grid, 256, GEMM_SMEM>>>(af, bf, out);
}

// round 14
// speedup vs baseline: 1.0615x; 1.0345x over previous
#include <cuda_runtime.h>
#include <cuda_fp16.h>
#include <cstdint>
#include <cfloat>

// Problem constants (fixed shapes for PQHotShared)
#define K_HOT   16384
#define R_DIM   64
#define D_DIM   4096
#define K_CB    2048
#define D_SUB   16
#define N_SV_U  (K_HOT * R_DIM / D_SUB)   // 65536
#define N_SV_B  (R_DIM * D_DIM / D_SUB)   // 16384

// Scratch (device globals — no allocation allowed)
__device__ __half g_Af[K_HOT * R_DIM];          // A as fp16 [m][k]
__device__ __half g_Bf[D_DIM * R_DIM];          // B^T as fp16 [n][k]

#define SW128(b) ((b) ^ (((b) >> 3) & 0x70))

__device__ __forceinline__ uint32_t smem_u32(const void* p) {
    uint32_t a;
    asm("{ .reg .u64 t; cvta.to.shared.u64 t, %1; cvt.u32.u64 %0, t; }"
        : "=r"(a) : "l"(p));
    return a;
}

__device__ __forceinline__ void ldmatrix_x4(uint32_t* r, uint32_t addr) {
    asm volatile("ldmatrix.sync.aligned.m8n8.x4.shared.b16 {%0,%1,%2,%3}, [%4];"
                 : "=r"(r[0]), "=r"(r[1]), "=r"(r[2]), "=r"(r[3]) : "r"(addr));
}

__device__ __forceinline__ void mma_f16(float* c, const uint32_t* a,
                                        const uint32_t* b) {
    asm volatile(
        "mma.sync.aligned.m16n8k16.row.col.f32.f16.f16.f32 "
        "{%0,%1,%2,%3}, {%4,%5,%6,%7}, {%8,%9}, {%0,%1,%2,%3};"
        : "+f"(c[0]), "+f"(c[1]), "+f"(c[2]), "+f"(c[3])
        : "r"(a[0]), "r"(a[1]), "r"(a[2]), "r"(a[3]), "r"(b[0]), "r"(b[1]));
}

__device__ __forceinline__ uint32_t pack_h2(float a, float b) {
    __half2 h = __floats2half2_rn(a, b);   // a -> low half (even k)
    return *(uint32_t*)&h;
}

// ---------------------------------------------------------------------------
// Fused PQ argmin via fp16-split m16n8k16 mma (round-12 scan math unchanged),
// with codebook conversion/packing folded into the chunk-load phase:
//  - thread task = (codeword c, quarter t): loads dims {2t,2t+1,2t+8,2t+9}
//    as two LDG.64, converts to fp16 hi/lo, stores ONE STS.128 in the
//    fragment-fused layout; hn computed via quad shfl reduction.
// One m16 tile per warp, 128 rows/block, 640 blocks.
// Blocks [0,512): U rows; [512,640): B rows (written transposed).
// ---------------------------------------------------------------------------
#define QROWS 128
#define QCH   512

__global__ __launch_bounds__(256) void pq_argmin_kernel(
    const float* __restrict__ U, const float* __restrict__ B,
    const float* __restrict__ rsU, const float* __restrict__ rsB,
    const float* __restrict__ cb,
    __half* __restrict__ Af, __half* __restrict__ Btf)
{
    __shared__ uint32_t cb_sh[QCH * 16];        // 32 KB, stride-16 rows
    __shared__ float hn_sh[QCH];                // 2 KB
    __shared__ int idx_sh[QROWS];

    const int tid = threadIdx.x;
    const int warp = tid >> 5, lane = tid & 31;
    const int g = lane >> 2, t = lane & 3;
    const bool isU = blockIdx.x < 512;
    const int svbase = isU ? blockIdx.x * QROWS : (blockIdx.x - 512) * QROWS;
    const float* Wp = isU ? U : B;

    // A fragments (fp16 hi/lo), one m16 tile per warp:
    // a0=(row g, kp t), a1=(row g+8, kp t), a2=(row g, kp t+4), a3=(row g+8, kp t+4)
    uint32_t ahi[4], alo[4];
    #pragma unroll
    for (int rh = 0; rh < 2; ++rh) {
        int r = svbase + warp * 16 + rh * 8 + g;
        int off; float rsv;
        if (isU) { off = (r >> 2) * 64 + (r & 3) * 16;     rsv = rsU[r >> 2]; }
        else     { off = (r >> 8) * 4096 + (r & 255) * 16; rsv = rsB[r >> 8]; }
        float v0 = Wp[off + 2 * t]     / rsv;
        float v1 = Wp[off + 2 * t + 1] / rsv;
        float v2 = Wp[off + 8 + 2 * t]     / rsv;
        float v3 = Wp[off + 8 + 2 * t + 1] / rsv;
        float h0 = __half2float(__float2half_rn(v0));
        float h1 = __half2float(__float2half_rn(v1));
        float h2 = __half2float(__float2half_rn(v2));
        float h3 = __half2float(__float2half_rn(v3));
        ahi[rh]     = pack_h2(h0, h1);
        ahi[2 + rh] = pack_h2(h2, h3);
        alo[rh]     = pack_h2(v0 - h0, v1 - h1);
        alo[2 + rh] = pack_h2(v2 - h2, v3 - h3);
    }

    float bs[2]; int bi[2];
    #pragma unroll
    for (int q = 0; q < 2; ++q) { bs[q] = -FLT_MAX; bi[q] = 0; }

    for (int ch = 0; ch < K_CB; ch += QCH) {
        __syncthreads();
        // Inline convert+pack: task i = (cw ci, quarter tq)
        #pragma unroll
        for (int it = 0; it < 8; ++it) {
            int i = tid + it * 256;
            int ci = i >> 2, tq = i & 3;
            const float* src = cb + (ch + ci) * D_SUB + 2 * tq;
            float2 pA = *(const float2*)(src);       // dims 2tq, 2tq+1
            float2 pB = *(const float2*)(src + 8);   // dims 2tq+8, 2tq+9
            float hA0 = __half2float(__float2half_rn(pA.x));
            float hA1 = __half2float(__float2half_rn(pA.y));
            float hB0 = __half2float(__float2half_rn(pB.x));
            float hB1 = __half2float(__float2half_rn(pB.y));
            uint4 w;
            w.x = pack_h2(hA0, hA1);                 // hi pair t
            w.y = pack_h2(hB0, hB1);                 // hi pair t+4
            w.z = pack_h2(pA.x - hA0, pA.y - hA1);   // lo pair t
            w.w = pack_h2(pB.x - hB0, pB.y - hB1);   // lo pair t+4
            *(uint4*)&cb_sh[ci * 16 + 4 * tq] = w;
            // hn: quad reduction over the 4 quarters of cw ci
            float part = fmaf(pA.x, pA.x, fmaf(pA.y, pA.y,
                         fmaf(pB.x, pB.x, pB.y * pB.y)));
            part += __shfl_xor_sync(0xffffffffu, part, 1);
            part += __shfl_xor_sync(0xffffffffu, part, 2);
            if (tq == 0) hn_sh[ci] = 0.5f * part;
        }
        __syncthreads();

        #pragma unroll 4
        for (int nt = 0; nt < QCH / 8; ++nt) {
            const int n0 = nt * 8;
            uint4 frag = *(const uint4*)&cb_sh[(n0 + g) * 16 + 4 * t];
            uint32_t bh[2] = {frag.x, frag.y};
            uint32_t bl[2] = {frag.z, frag.w};
            float2 hnp = *(const float2*)&hn_sh[n0 + 2 * t];
            const int base = ch + n0 + 2 * t;
            float c[4] = {-hnp.x, -hnp.y, -hnp.x, -hnp.y};
            mma_f16(c, ahi, bh);
            mma_f16(c, ahi, bl);
            mma_f16(c, alo, bh);
            if (c[0] > bs[0]) { bs[0] = c[0]; bi[0] = base; }
            if (c[1] > bs[0]) { bs[0] = c[1]; bi[0] = base + 1; }
            if (c[2] > bs[1]) { bs[1] = c[2]; bi[1] = base; }
            if (c[3] > bs[1]) { bs[1] = c[3]; bi[1] = base + 1; }
        }
    }

    // Reduce argmax across the 4 t-lanes of each row quad (tie -> smaller idx)
    #pragma unroll
    for (int q = 0; q < 2; ++q) {
        float s = bs[q]; int i0 = bi[q];
        #pragma unroll
        for (int d = 1; d <= 2; d <<= 1) {
            float so = __shfl_xor_sync(0xffffffffu, s, d);
            int   io = __shfl_xor_sync(0xffffffffu, i0, d);
            if (so > s || (so == s && io < i0)) { s = so; i0 = io; }
        }
        if (t == 0)
            idx_sh[warp * 16 + q * 8 + g] = i0;
    }
    __syncwarp();

    // Dequant write: lanes 0..15 each own one row of the warp's 16.
    if (lane < 16) {
        const int rloc = warp * 16 + lane;
        const int w = idx_sh[rloc];
        const int r = svbase + rloc;
        const float* cbr = cb + w * D_SUB;
        if (isU) {
            const int urow = r >> 2;
            const float rsv = rsU[urow];
            const int off = urow * 64 + (r & 3) * 16;
            uint32_t* df = (uint32_t*)(Af + off);
            #pragma unroll
            for (int p = 0; p < 8; ++p)
                df[p] = pack_h2(cbr[2 * p] * rsv, cbr[2 * p + 1] * rsv);
        } else {
            const int brow = r >> 8;
            const float rsv = rsB[brow];
            const int nb = (r & 255) * 16;
            #pragma unroll
            for (int j = 0; j < D_SUB; ++j)
                Btf[(nb + j) * 64 + brow] = __float2half_rn(cbr[j] * rsv);
        }
    }
}

// ---------------------------------------------------------------------------
// fp16 single-pass GEMM on mma.sync (rounds 7-12) with streaming C stores:
// C[16384,4096] = Af @ Bf^T, fp32 acc. C is write-once -> st.global.cs.
// ---------------------------------------------------------------------------
#define OFF_AF 0
#define OFF_BF 16384
#define GEMM_SMEM (2 * 16384)

__device__ __forceinline__ void load_tile_128x64(
    char* smem, int off, const __half* __restrict__ src, int tid)
{
    #pragma unroll
    for (int it = 0; it < 4; ++it) {
        int i = tid + it * 256;
        int m = i >> 3, q = i & 7;
        uint32_t b = (uint32_t)(m * 128 + q * 16);
        *(uint4*)(smem + off + SW128(b)) = ((const uint4*)(src + m * 64))[q];
    }
}

__global__ __launch_bounds__(256, 2) void mma_gemm_kernel(
    const __half* __restrict__ Af, const __half* __restrict__ Bf,
    float* __restrict__ C)
{
    extern __shared__ char smem[];
    const uint32_t sbase = smem_u32(smem);
    const int tid = threadIdx.x;
    const int wid = tid >> 5, lane = tid & 31;
    const int row0 = blockIdx.y * 128;
    const int col0 = blockIdx.x * 128;

    load_tile_128x64(smem, OFF_AF, Af + (size_t)row0 * R_DIM, tid);
    load_tile_128x64(smem, OFF_BF, Bf + (size_t)col0 * R_DIM, tid);
    __syncthreads();

    const int warp_m = wid & 3;
    const int warp_n = wid >> 2;
    const int mbase = warp_m * 32;
    const int nbase = warp_n * 64;

    const int a_row = mbase + (lane & 15);
    const int a_kb  = (lane >> 4) * 16;
    const int b_nrow = nbase + (lane & 7) + (lane >> 4) * 8;
    const int b_kb   = ((lane >> 3) & 1) * 16;

    float acc[2][8][4];
    #pragma unroll
    for (int mt = 0; mt < 2; ++mt)
        #pragma unroll
        for (int nt = 0; nt < 8; ++nt)
            #pragma unroll
            for (int q = 0; q < 4; ++q) acc[mt][nt][q] = 0.f;

    #pragma unroll
    for (int k = 0; k < 4; ++k) {
        uint32_t a[2][4];
        #pragma unroll
        for (int mt = 0; mt < 2; ++mt) {
            uint32_t b = (uint32_t)((a_row + mt * 16) * 128 + k * 32 + a_kb);
            ldmatrix_x4(a[mt], sbase + OFF_AF + SW128(b));
        }
        uint32_t bf[8][2];
        #pragma unroll
        for (int np = 0; np < 4; ++np) {
            uint32_t b = (uint32_t)((b_nrow + np * 16) * 128 + k * 32 + b_kb);
            uint32_t r[4];
            ldmatrix_x4(r, sbase + OFF_BF + SW128(b));
            bf[np * 2][0] = r[0]; bf[np * 2][1] = r[1];
            bf[np * 2 + 1][0] = r[2]; bf[np * 2 + 1][1] = r[3];
        }
        #pragma unroll
        for (int mt = 0; mt < 2; ++mt)
            #pragma unroll
            for (int nt = 0; nt < 8; ++nt)
                mma_f16(acc[mt][nt], a[mt], bf[nt]);
    }

    const int g = lane >> 2, t = lane & 3;
    #pragma unroll
    for (int mt = 0; mt < 2; ++mt) {
        float* Cr0 = C + (size_t)(row0 + mbase + mt * 16 + g) * D_DIM + col0 + nbase;
        float* Cr1 = Cr0 + 8 * D_DIM;
        #pragma unroll
        for (int nt = 0; nt < 8; ++nt) {
            __stcs((float2*)(Cr0 + nt * 8 + t * 2),
                   make_float2(acc[mt][nt][0], acc[mt][nt][1]));
            __stcs((float2*)(Cr1 + nt * 8 + t * 2),
                   make_float2(acc[mt][nt][2], acc[mt][nt][3]));
        }
    }
}

// ---------------------------------------------------------------------------
extern "C" void kernel_launch(void* const* d_in, const int* in_sizes, int n_in,
                              void* d_out, int out_size)
{
    (void)in_sizes; (void)n_in; (void)out_size;
    const float* U   = (const float*)d_in[0];
    const float* B   = (const float*)d_in[1];
    const float* rsU = (const float*)d_in[2];
    const float* rsB = (const float*)d_in[3];
    const float* cb  = (const float*)d_in[4];
    float* out = (float*)d_out;

    __half *af, *bf;
    cudaGetSymbolAddress((void**)&af, g_Af);
    cudaGetSymbolAddress((void**)&bf, g_Bf);

    pq_argmin_kernel<<<640, 256>>>(U, B, rsU, rsB, cb, af, bf);

    cudaFuncSetAttribute(mma_gemm_kernel,
                         cudaFuncAttributeMaxDynamicSharedMemorySize, GEMM_SMEM);
    dim3 grid(D_DIM / 128, K_HOT / 128);
    mma_gemm_kernel<<<grid, 256, GEMM_SMEM>>>(af, bf, out);
}